// round 14
// baseline (speedup 1.0000x reference)
#include <cuda_runtime.h>
#include <cstdint>
#include <math.h>

#define B_    64
#define C_    256
#define T_    1024
#define H_    512
#define S_TOT 192
#define S_RX0 64
#define BETA  0.9f
#define THR   0.75f
#define LCAP  120      // per-timestep active-index list capacity (u16, padded to mult of 4)
#define TT    128      // timesteps per k2a CTA tile
#define OB    64       // output channels per k2a CTA
#define WQN   16964    // ints per W image block (257*66 = 16962, +2 pad -> 4241 uint4)

// ---- output layout (flattened tuple, float32) ----
#define OUT_D  0
#define OUT_A  (B_*H_)
#define OUT_E  (2*B_*H_)
#define OUT_RX (3*B_*H_)
#define OUT_PX (3*B_*H_ + B_*2*C_*T_)

// ---- static device scratch ----
__device__ float          g_acc   [(size_t)S_TOT * T_ * C_];  // mixed (pre-bias) [s][t][c]
__device__ unsigned int   g_trace [128 * C_ * 32];            // rx spike bits [rb][c][t/32]
__device__ int            g_spkcnt[S_TOT * C_];
__device__ float          g_feat  [3 * B_ * C_];
__device__ uint4          g_idx_w [S_TOT * T_ * (LCAP/8)];    // u16 index lists (premul x33)
__device__ unsigned short g_cnt   [S_TOT * T_];
__device__ __align__(16) int g_Wq [8 * WQN];                  // quantized W images [img2][oblk4]

// ============================================================================
// K0q: pre-quantize W_tx / W_rx into smem-image layout: per (img, o-block),
// W_q[c*66 + r] = rint(W[(o0+r)*256 + c] * 2^30), plus zero row + pad.
// grid dim3(2,4) x 256 threads.
// ============================================================================
__global__ void k0q(const float* __restrict__ W_tx, const float* __restrict__ W_rx)
{
    const int img = blockIdx.x, ob = blockIdx.y;
    const float* W = img ? W_rx : W_tx;
    int* dst = g_Wq + (img * 4 + ob) * WQN;
    const int o0 = ob * OB;

    #pragma unroll 4
    for (int idx = threadIdx.x; idx < OB * C_; idx += 256) {
        const int r = idx >> 8, c = idx & 255;
        dst[c * 66 + r] = __float2int_rn(W[(size_t)(o0 + r) * C_ + c] * 1073741824.0f);
    }
    if (threadIdx.x < 68) dst[256 * 66 + threadIdx.x] = 0;   // zero row + pad
}

// ============================================================================
// K1: build per-timestep active-channel index lists (ballot compaction).
// Indices PRE-MULTIPLIED by 33 (int2 stride of W image row). Pad to mult of 4.
// grid: 192*32 CTAs, 256 threads. CTA = (s, 32-timestep tile)
// ============================================================================
__global__ void k1_pack(const float* __restrict__ tx, const float* __restrict__ rxsp)
{
    __shared__ float tile[256 * 33];
    __shared__ __align__(16) unsigned short lists[32 * LCAP];
    __shared__ int cnts[32];

    const int s  = blockIdx.x >> 5;
    const int t0 = (blockIdx.x & 31) * 32;
    const float* base = (s < S_RX0) ? (tx + (size_t)s * C_ * T_)
                                    : (rxsp + (size_t)(s - S_RX0) * C_ * T_);
    const int w = threadIdx.x >> 5, l = threadIdx.x & 31;

    #pragma unroll 4
    for (int i = 0; i < 32; i++) {
        int c = i * 8 + w;
        tile[c * 33 + l] = base[(size_t)c * T_ + t0 + l];
    }
    __syncthreads();

    for (int tt = w * 4; tt < w * 4 + 4; tt++) {
        int cnt = 0;
        #pragma unroll
        for (int g = 0; g < 8; g++) {
            float v = tile[(g * 32 + l) * 33 + tt];
            unsigned m = __ballot_sync(0xffffffffu, v > 0.5f);
            if (v > 0.5f) {
                int pos = cnt + __popc(m & ((1u << l) - 1u));
                if (pos < LCAP) lists[tt * LCAP + pos] = (unsigned short)((g * 32 + l) * 33);
            }
            cnt += __popc(m);
        }
        if (cnt > 116) cnt = 116;               // astronomically unlikely
        int padded = (cnt + 3) & ~3;
        if (l < padded - cnt) lists[tt * LCAP + cnt + l] = (unsigned short)(256 * 33); // zero row
        if (l == 0) cnts[tt] = padded;
    }
    __syncthreads();

    uint4* dst = g_idx_w + (size_t)(s * T_ + t0) * (LCAP/8);
    const uint4* srcw = (const uint4*)lists;
    for (int i = threadIdx.x; i < 32 * (LCAP/8); i += 256) dst[i] = srcw[i];
    if (threadIdx.x < 32)
        g_cnt[s * T_ + t0 + threadIdx.x] = (unsigned short)cnts[threadIdx.x];
}

// ============================================================================
// K2a v7: sparse mix, EXACT uint32 accumulation of pre-quantized W.
// CTA = (s_base + bz, o-block, 128-t tile). Copy prologue from g_Wq.
// 256 threads, warp = 16 t's, lane = 2 outputs via LDS.64. 2 CTAs/SM.
// Inner loop: 8-active groups (unroll 2) + optional 4-active epilogue.
// smem: W image 67856B @0; lists 30720B @67856; cnt 128*u16 @98576. = 98832.
// ============================================================================
__global__ void __launch_bounds__(256) k2a_mix(int s_base)
{
    extern __shared__ unsigned char smem_raw[];
    int*            W_shi  = (int*)smem_raw;
    unsigned short* lists  = (unsigned short*)(smem_raw + 67856);
    unsigned short* cnt_sh = (unsigned short*)(smem_raw + 98576);

    const int tid = threadIdx.x;
    const int s   = s_base + blockIdx.z;
    const int ob  = blockIdx.y;
    const int t0  = blockIdx.x * TT;
    const int o0  = ob * OB;
    const int img = (s < S_RX0) ? 0 : 1;

    // ---- prologue: copy pre-quantized W image (4241 uint4, L2-resident)
    {
        const uint4* wsrc = (const uint4*)(g_Wq + (img * 4 + ob) * WQN);
        uint4* wdst = (uint4*)W_shi;
        #pragma unroll 4
        for (int i = tid; i < 4241; i += 256) wdst[i] = wsrc[i];
    }
    // ---- stage lists + counts for this 128-t tile
    {
        const uint4* src = g_idx_w + (size_t)(s * T_ + t0) * (LCAP/8);
        uint4* dstl = (uint4*)lists;
        #pragma unroll 2
        for (int i = tid; i < TT * (LCAP/8); i += 256) dstl[i] = src[i];
        if (tid < TT) cnt_sh[tid] = g_cnt[s * T_ + t0 + tid];
    }
    __syncthreads();

    const int w = tid >> 5, lane = tid & 31;
    const uint2* Wt2 = (const uint2*)W_shi + lane;   // lane's int2 column

    #pragma unroll 1
    for (int tslot = 0; tslot < TT / 8; ++tslot) {
        const int tt = w * (TT / 8) + tslot;
        const int cnt = cnt_sh[tt];
        const int n8 = cnt >> 3;
        const unsigned short* lw16 = lists + tt * LCAP;
        const uint4* lw = (const uint4*)lw16;
        unsigned a0x = 0u, a0y = 0u, a1x = 0u, a1y = 0u;
        unsigned a2x = 0u, a2y = 0u, a3x = 0u, a3y = 0u;
        #pragma unroll 2
        for (int j = 0; j < n8; ++j) {
            uint4 v = lw[j];
            uint2 w0 = Wt2[v.x & 0xffffu];  a0x += w0.x; a0y += w0.y;
            uint2 w1 = Wt2[v.x >> 16];      a1x += w1.x; a1y += w1.y;
            uint2 w2 = Wt2[v.y & 0xffffu];  a2x += w2.x; a2y += w2.y;
            uint2 w3 = Wt2[v.y >> 16];      a3x += w3.x; a3y += w3.y;
            uint2 w4 = Wt2[v.z & 0xffffu];  a0x += w4.x; a0y += w4.y;
            uint2 w5 = Wt2[v.z >> 16];      a1x += w5.x; a1y += w5.y;
            uint2 w6 = Wt2[v.w & 0xffffu];  a2x += w6.x; a2y += w6.y;
            uint2 w7 = Wt2[v.w >> 16];      a3x += w7.x; a3y += w7.y;
        }
        if (cnt & 4) {   // 4-active epilogue group (pad-4 lists)
            const uint2 v = *(const uint2*)(lw16 + (n8 << 3));
            uint2 w0 = Wt2[v.x & 0xffffu];  a0x += w0.x; a0y += w0.y;
            uint2 w1 = Wt2[v.x >> 16];      a1x += w1.x; a1y += w1.y;
            uint2 w2 = Wt2[v.y & 0xffffu];  a2x += w2.x; a2y += w2.y;
            uint2 w3 = Wt2[v.y >> 16];      a3x += w3.x; a3y += w3.y;
        }
        const int sx = (int)((a0x + a1x) + (a2x + a3x));
        const int sy = (int)((a0y + a1y) + (a2y + a3y));
        float2 r;
        r.x = (float)sx * 0x1p-30f;
        r.y = (float)sy * 0x1p-30f;
        *(float2*)(g_acc + (size_t)(s * T_ + t0 + tt) * C_ + o0 + 2 * lane) = r;
    }
}

// ============================================================================
// K2b: LIF recurrence, double-buffered loads + branch-free spike update.
// CTA per sequence (s = s0 + blockIdx.x), thread per channel c.
// ============================================================================
__device__ __forceinline__ void k2b_load(float* buf, const float* ap, int t32)
{
    #pragma unroll
    for (int k = 0; k < 32; ++k)
        buf[k] = ap[(size_t)(t32 * 32 + k) * C_];
}

__device__ __forceinline__ void k2b_step(const float* buf, float bias,
                                         float& m, float& sub, unsigned& word)
{
    word = 0u;
    #pragma unroll
    for (int k = 0; k < 32; ++k) {
        m = BETA * m + (buf[k] + bias) - sub;
        const unsigned neg = (unsigned)(__float_as_int(THR - m) >> 31);  // all-ones iff m > THR
        sub = __uint_as_float(neg & 0x3F400000u);                        // 0.75f or 0.0f (exact)
        word |= (neg & 1u) << k;
    }
}

__global__ void __launch_bounds__(256) k2b_scan(const float* __restrict__ b_tx,
                                                const float* __restrict__ b_rx,
                                                int s0)
{
    const int s = s0 + blockIdx.x, c = threadIdx.x;
    const bool is_rx = (s >= S_RX0);
    const float bias = is_rx ? b_rx[c] : b_tx[c];
    const float* ap = g_acc + (size_t)s * T_ * C_ + c;
    const unsigned tb = is_rx ? ((unsigned)(s - S_RX0) * C_ + c) * 32u : 0u;

    float m = 0.0f, sub = 0.0f;
    int cnt = 0;
    float bufA[32], bufB[32];

    k2b_load(bufA, ap, 0);
    #pragma unroll 1
    for (int i = 0; i < 16; ++i) {
        unsigned w0, w1;
        k2b_load(bufB, ap, 2 * i + 1);
        k2b_step(bufA, bias, m, sub, w0);
        if (is_rx) g_trace[tb + 2 * i] = w0;
        cnt += __popc(w0);
        if (i < 15) k2b_load(bufA, ap, 2 * i + 2);
        k2b_step(bufB, bias, m, sub, w1);
        if (is_rx) g_trace[tb + 2 * i + 1] = w1;
        cnt += __popc(w1);
    }
    g_spkcnt[s * C_ + c] = cnt;
}

// ============================================================================
// K3: expand rx spike bits -> float32 trace in d_out (coalesced LUT expansion)
// ============================================================================
__global__ void k3_expand(float* __restrict__ out)
{
    __shared__ float4 lut[16];
    if (threadIdx.x < 16)
        lut[threadIdx.x] = make_float4((float)(threadIdx.x & 1), (float)((threadIdx.x >> 1) & 1),
                                       (float)((threadIdx.x >> 2) & 1), (float)((threadIdx.x >> 3) & 1));
    __syncthreads();

    const int row = blockIdx.x * 8 + (threadIdx.x >> 5);   // 0..32767
    const int l   = threadIdx.x & 31;
    const unsigned word = g_trace[(size_t)row * 32 + l];
    float4* dst = (float4*)(out + OUT_RX + (size_t)row * T_);
    #pragma unroll
    for (int k = 0; k < 8; k++) {
        const int t4   = k * 32 + l;
        const unsigned wsrc = __shfl_sync(0xffffffffu, word, t4 >> 3);
        const unsigned nib  = (wsrc >> ((t4 & 7) * 4)) & 0xFu;
        dst[t4] = lut[nib];
    }
}

// ============================================================================
// K4a: features + layernorm + spike_proxy
// ============================================================================
__device__ __forceinline__ float blk_sum(float v, float* red, int c)
{
    red[c] = v; __syncthreads();
    #pragma unroll
    for (int off = 128; off > 0; off >>= 1) {
        if (c < off) red[c] += red[c + off];
        __syncthreads();
    }
    float s = red[0]; __syncthreads();
    return s;
}

__global__ void k4a_feat(float* __restrict__ out)
{
    __shared__ float red[256];
    const int b = blockIdx.x, c = threadIdx.x;
    const int cd = g_spkcnt[b * C_ + c];
    const int cl = g_spkcnt[(S_RX0 + b * 2 + 0) * C_ + c];
    const int cr = g_spkcnt[(S_RX0 + b * 2 + 1) * C_ + c];

    out[OUT_PX + (size_t)(b * 2 + 0) * C_ + c] = (float)cl;
    out[OUT_PX + (size_t)(b * 2 + 1) * C_ + c] = (float)cr;

    float f[3];
    f[0] = (float)cd        * (1.0f / 1024.0f);
    f[1] = (float)(cl - cr) * (1.0f / 1024.0f);
    f[2] = (float)(cl + cr) * (1.0f / 1024.0f);

    #pragma unroll
    for (int typ = 0; typ < 3; typ++) {
        const float mu = blk_sum(f[typ], red, c) * (1.0f / 256.0f);
        const float xc = f[typ] - mu;
        const float var = blk_sum(xc * xc, red, c) * (1.0f / 256.0f);
        g_feat[(typ * B_ + b) * C_ + c] = xc / sqrtf(var + 1e-5f);
    }
}

// ============================================================================
// K4b: heads — [64x256]@[256x512]^T + bias, gain, residual, relu.
// ============================================================================
__global__ void k4b_head(const float* __restrict__ Wd, const float* __restrict__ bd,
                         const float* __restrict__ Wa, const float* __restrict__ ba,
                         const float* __restrict__ We, const float* __restrict__ be,
                         const float* __restrict__ base_d, const float* __restrict__ base_a,
                         const float* __restrict__ base_e,
                         const float* __restrict__ gd, const float* __restrict__ ga,
                         const float* __restrict__ ge,
                         float* __restrict__ out)
{
    extern __shared__ float x_sh[];   // 64*256 floats
    const int typ = blockIdx.x >> 6;
    const int h0  = (blockIdx.x & 63) * 8;

    const float* feat = g_feat + (size_t)typ * B_ * C_;
    for (int i = threadIdx.x; i < B_ * C_; i += 256) x_sh[i] = feat[i];
    __syncthreads();

    const float* Wm   = (typ == 0) ? Wd : (typ == 1) ? Wa : We;
    const float* bm   = (typ == 0) ? bd : (typ == 1) ? ba : be;
    const float* bsp  = (typ == 0) ? base_d : (typ == 1) ? base_a : base_e;
    const float  g    = (typ == 0) ? *gd : (typ == 1) ? *ga : *ge;
    const float  sg   = 0.3f / (1.0f + expf(-g));
    const size_t ooff = (typ == 0) ? OUT_D : (typ == 1) ? OUT_A : OUT_E;

    const int lane = threadIdx.x & 31;
    const int h    = h0 + (threadIdx.x >> 5);

    const float4* wrow = (const float4*)(Wm + (size_t)h * C_);
    const float4 w0 = wrow[lane * 2];
    const float4 w1 = wrow[lane * 2 + 1];
    const float  bh = bm[h];

    for (int b = 0; b < B_; b++) {
        const float4* xb = (const float4*)(x_sh + b * C_ + lane * 8);
        const float4 x0 = xb[0], x1 = xb[1];
        float p = w0.x * x0.x + w0.y * x0.y + w0.z * x0.z + w0.w * x0.w
                + w1.x * x1.x + w1.y * x1.y + w1.z * x1.z + w1.w * x1.w;
        #pragma unroll
        for (int off = 16; off > 0; off >>= 1)
            p += __shfl_xor_sync(0xffffffffu, p, off);
        if (lane == 0) {
            const float r = p + bh;
            const float v = bsp[(size_t)b * H_ + h] + sg * r;
            out[ooff + (size_t)b * H_ + h] = v > 0.0f ? v : 0.0f;
        }
    }
}

// ============================================================================
extern "C" void kernel_launch(void* const* d_in, const int* in_sizes, int n_in,
                              void* d_out, int out_size)
{
    const float* tx    = (const float*)d_in[0];
    const float* rxsp  = (const float*)d_in[1];
    const float* bsd   = (const float*)d_in[2];
    const float* bsa   = (const float*)d_in[3];
    const float* bse   = (const float*)d_in[4];
    const float* W_tx  = (const float*)d_in[5];
    const float* b_tx  = (const float*)d_in[6];
    const float* W_rx  = (const float*)d_in[7];
    const float* b_rx  = (const float*)d_in[8];
    const float* Wd    = (const float*)d_in[9];
    const float* bd    = (const float*)d_in[10];
    const float* Wa    = (const float*)d_in[11];
    const float* ba    = (const float*)d_in[12];
    const float* We    = (const float*)d_in[13];
    const float* be    = (const float*)d_in[14];
    const float* gd    = (const float*)d_in[15];
    const float* ga    = (const float*)d_in[16];
    const float* ge    = (const float*)d_in[17];
    float* out = (float*)d_out;

    static bool inited = false;
    static cudaStream_t sA = 0, sB = 0;
    static cudaEvent_t evFork = 0, evA = 0, evB = 0, evScanA = 0, evScanB = 0;
    if (!inited) {
        cudaFuncSetAttribute(k2a_mix, cudaFuncAttributeMaxDynamicSharedMemorySize, 98832);
        cudaFuncSetAttribute(k4b_head, cudaFuncAttributeMaxDynamicSharedMemorySize, 65536);
        cudaStreamCreateWithFlags(&sA, cudaStreamNonBlocking);
        cudaStreamCreateWithFlags(&sB, cudaStreamNonBlocking);
        cudaEventCreateWithFlags(&evFork,  cudaEventDisableTiming);
        cudaEventCreateWithFlags(&evA,     cudaEventDisableTiming);
        cudaEventCreateWithFlags(&evB,     cudaEventDisableTiming);
        cudaEventCreateWithFlags(&evScanA, cudaEventDisableTiming);
        cudaEventCreateWithFlags(&evScanB, cudaEventDisableTiming);
        inited = true;
    }

    k0q<<<dim3(2, 4), 256>>>(W_tx, W_rx);
    k1_pack<<<S_TOT * 32, 256>>>(tx, rxsp);
    cudaEventRecord(evFork, 0);

    // ---- big crossbar-bound work on sA, split into s-halves
    cudaStreamWaitEvent(sA, evFork, 0);
    k2a_mix<<<dim3(T_ / TT, C_ / OB, 96), 256, 98832, sA>>>(0);
    cudaEventRecord(evA, sA);
    k2a_mix<<<dim3(T_ / TT, C_ / OB, 96), 256, 98832, sA>>>(96);
    cudaEventRecord(evB, sA);

    // ---- small DRAM/latency-bound scans on sB, overlapping k2a's 2nd half
    cudaStreamWaitEvent(sB, evA, 0);
    k2b_scan<<<96, 256, 0, sB>>>(b_tx, b_rx, 0);
    cudaEventRecord(evScanA, sB);
    cudaStreamWaitEvent(sB, evB, 0);
    k2b_scan<<<96, 256, 0, sB>>>(b_tx, b_rx, 96);
    cudaEventRecord(evScanB, sB);

    // ---- join + tail
    cudaStreamWaitEvent(0, evScanA, 0);
    cudaStreamWaitEvent(0, evScanB, 0);
    k3_expand<<<4096, 256>>>(out);
    k4a_feat<<<B_, 256>>>(out);
    k4b_head<<<3 * 64, 256, 65536>>>(Wd, bd, Wa, ba, We, be, bsd, bsa, bse, gd, ga, ge, out);
}

// round 15
// speedup vs baseline: 1.0709x; 1.0709x over previous
#include <cuda_runtime.h>
#include <cstdint>
#include <math.h>

#define B_    64
#define C_    256
#define T_    1024
#define H_    512
#define S_TOT 192
#define S_RX0 64
#define BETA  0.9f
#define THR   0.75f
#define LCAP  120      // per-timestep active-index list capacity (u16, padded to mult of 4)
#define TT    128      // timesteps per k2a CTA tile
#define OB    64       // output channels per k2a CTA
#define WQN   16964    // ints per W image block (257*66 = 16962, +2 pad -> 4241 uint4)

// ---- output layout (flattened tuple, float32) ----
#define OUT_D  0
#define OUT_A  (B_*H_)
#define OUT_E  (2*B_*H_)
#define OUT_RX (3*B_*H_)
#define OUT_PX (3*B_*H_ + B_*2*C_*T_)

// ---- static device scratch ----
__device__ float          g_acc   [(size_t)S_TOT * T_ * C_];  // mixed (pre-bias) [s][t][c]
__device__ unsigned int   g_trace [128 * C_ * 32];            // rx spike bits [rb][c][t/32]
__device__ int            g_spkcnt[S_TOT * C_];
__device__ float          g_feat  [3 * B_ * C_];
__device__ uint4          g_idx_w [S_TOT * T_ * (LCAP/8)];    // u16 index lists (premul x33)
__device__ unsigned short g_cnt   [S_TOT * T_];
__device__ __align__(16) int g_Wq [8 * WQN];                  // quantized W images [img2][oblk4]

// ============================================================================
// K0q: pre-quantize W_tx / W_rx into smem-image layout: per (img, o-block),
// W_q[c*66 + r] = rint(W[(o0+r)*256 + c] * 2^30), plus zero row + pad.
// grid dim3(2,4) x 256 threads.
// ============================================================================
__global__ void k0q(const float* __restrict__ W_tx, const float* __restrict__ W_rx)
{
    const int img = blockIdx.x, ob = blockIdx.y;
    const float* W = img ? W_rx : W_tx;
    int* dst = g_Wq + (img * 4 + ob) * WQN;
    const int o0 = ob * OB;

    #pragma unroll 4
    for (int idx = threadIdx.x; idx < OB * C_; idx += 256) {
        const int r = idx >> 8, c = idx & 255;
        dst[c * 66 + r] = __float2int_rn(W[(size_t)(o0 + r) * C_ + c] * 1073741824.0f);
    }
    if (threadIdx.x < 68) dst[256 * 66 + threadIdx.x] = 0;   // zero row + pad
}

// ============================================================================
// K1: build per-timestep active-channel index lists (ballot compaction).
// Indices PRE-MULTIPLIED by 33 (int2 stride of W image row). Pad to mult of 4.
// grid: 192*32 CTAs, 256 threads. CTA = (s, 32-timestep tile)
// ============================================================================
__global__ void k1_pack(const float* __restrict__ tx, const float* __restrict__ rxsp)
{
    __shared__ float tile[256 * 33];
    __shared__ __align__(16) unsigned short lists[32 * LCAP];
    __shared__ int cnts[32];

    const int s  = blockIdx.x >> 5;
    const int t0 = (blockIdx.x & 31) * 32;
    const float* base = (s < S_RX0) ? (tx + (size_t)s * C_ * T_)
                                    : (rxsp + (size_t)(s - S_RX0) * C_ * T_);
    const int w = threadIdx.x >> 5, l = threadIdx.x & 31;

    #pragma unroll 4
    for (int i = 0; i < 32; i++) {
        int c = i * 8 + w;
        tile[c * 33 + l] = base[(size_t)c * T_ + t0 + l];
    }
    __syncthreads();

    for (int tt = w * 4; tt < w * 4 + 4; tt++) {
        int cnt = 0;
        #pragma unroll
        for (int g = 0; g < 8; g++) {
            float v = tile[(g * 32 + l) * 33 + tt];
            unsigned m = __ballot_sync(0xffffffffu, v > 0.5f);
            if (v > 0.5f) {
                int pos = cnt + __popc(m & ((1u << l) - 1u));
                if (pos < LCAP) lists[tt * LCAP + pos] = (unsigned short)((g * 32 + l) * 33);
            }
            cnt += __popc(m);
        }
        if (cnt > 116) cnt = 116;               // astronomically unlikely
        int padded = (cnt + 3) & ~3;
        if (l < padded - cnt) lists[tt * LCAP + cnt + l] = (unsigned short)(256 * 33); // zero row
        if (l == 0) cnts[tt] = padded;
    }
    __syncthreads();

    uint4* dst = g_idx_w + (size_t)(s * T_ + t0) * (LCAP/8);
    const uint4* srcw = (const uint4*)lists;
    for (int i = threadIdx.x; i < 32 * (LCAP/8); i += 256) dst[i] = srcw[i];
    if (threadIdx.x < 32)
        g_cnt[s * T_ + t0 + threadIdx.x] = (unsigned short)cnts[threadIdx.x];
}

// ============================================================================
// K2a v7: sparse mix, EXACT uint32 accumulation of pre-quantized W.
// CTA = (s, o-block, 128-t tile), full grid (8 x 4 x 192), sequential launch.
// 256 threads, warp = 16 t's, lane = 2 outputs via LDS.64. 2 CTAs/SM.
// Inner loop: 8-active groups (unroll 2) + optional 4-active epilogue.
// smem: W image 67856B @0; lists 30720B @67856; cnt 128*u16 @98576. = 98832.
// ============================================================================
__global__ void __launch_bounds__(256) k2a_mix()
{
    extern __shared__ unsigned char smem_raw[];
    int*            W_shi  = (int*)smem_raw;
    unsigned short* lists  = (unsigned short*)(smem_raw + 67856);
    unsigned short* cnt_sh = (unsigned short*)(smem_raw + 98576);

    const int tid = threadIdx.x;
    const int s   = blockIdx.z;
    const int ob  = blockIdx.y;
    const int t0  = blockIdx.x * TT;
    const int o0  = ob * OB;
    const int img = (s < S_RX0) ? 0 : 1;

    // ---- prologue: copy pre-quantized W image (4241 uint4, L2-resident)
    {
        const uint4* wsrc = (const uint4*)(g_Wq + (img * 4 + ob) * WQN);
        uint4* wdst = (uint4*)W_shi;
        #pragma unroll 4
        for (int i = tid; i < 4241; i += 256) wdst[i] = wsrc[i];
    }
    // ---- stage lists + counts for this 128-t tile
    {
        const uint4* src = g_idx_w + (size_t)(s * T_ + t0) * (LCAP/8);
        uint4* dstl = (uint4*)lists;
        #pragma unroll 2
        for (int i = tid; i < TT * (LCAP/8); i += 256) dstl[i] = src[i];
        if (tid < TT) cnt_sh[tid] = g_cnt[s * T_ + t0 + tid];
    }
    __syncthreads();

    const int w = tid >> 5, lane = tid & 31;
    const uint2* Wt2 = (const uint2*)W_shi + lane;   // lane's int2 column

    #pragma unroll 1
    for (int tslot = 0; tslot < TT / 8; ++tslot) {
        const int tt = w * (TT / 8) + tslot;
        const int cnt = cnt_sh[tt];
        const int n8 = cnt >> 3;
        const unsigned short* lw16 = lists + tt * LCAP;
        const uint4* lw = (const uint4*)lw16;
        unsigned a0x = 0u, a0y = 0u, a1x = 0u, a1y = 0u;
        unsigned a2x = 0u, a2y = 0u, a3x = 0u, a3y = 0u;
        #pragma unroll 2
        for (int j = 0; j < n8; ++j) {
            uint4 v = lw[j];
            uint2 w0 = Wt2[v.x & 0xffffu];  a0x += w0.x; a0y += w0.y;
            uint2 w1 = Wt2[v.x >> 16];      a1x += w1.x; a1y += w1.y;
            uint2 w2 = Wt2[v.y & 0xffffu];  a2x += w2.x; a2y += w2.y;
            uint2 w3 = Wt2[v.y >> 16];      a3x += w3.x; a3y += w3.y;
            uint2 w4 = Wt2[v.z & 0xffffu];  a0x += w4.x; a0y += w4.y;
            uint2 w5 = Wt2[v.z >> 16];      a1x += w5.x; a1y += w5.y;
            uint2 w6 = Wt2[v.w & 0xffffu];  a2x += w6.x; a2y += w6.y;
            uint2 w7 = Wt2[v.w >> 16];      a3x += w7.x; a3y += w7.y;
        }
        if (cnt & 4) {   // 4-active epilogue group (pad-4 lists)
            const uint2 v = *(const uint2*)(lw16 + (n8 << 3));
            uint2 w0 = Wt2[v.x & 0xffffu];  a0x += w0.x; a0y += w0.y;
            uint2 w1 = Wt2[v.x >> 16];      a1x += w1.x; a1y += w1.y;
            uint2 w2 = Wt2[v.y & 0xffffu];  a2x += w2.x; a2y += w2.y;
            uint2 w3 = Wt2[v.y >> 16];      a3x += w3.x; a3y += w3.y;
        }
        const int sx = (int)((a0x + a1x) + (a2x + a3x));
        const int sy = (int)((a0y + a1y) + (a2y + a3y));
        float2 r;
        r.x = (float)sx * 0x1p-30f;
        r.y = (float)sy * 0x1p-30f;
        *(float2*)(g_acc + (size_t)(s * T_ + t0 + tt) * C_ + o0 + 2 * lane) = r;
    }
}

// ============================================================================
// K2b: LIF recurrence, double-buffered loads + branch-free spike update.
// grid 192 x 256; CTA per sequence, thread per channel.
// ============================================================================
__device__ __forceinline__ void k2b_load(float* buf, const float* ap, int t32)
{
    #pragma unroll
    for (int k = 0; k < 32; ++k)
        buf[k] = ap[(size_t)(t32 * 32 + k) * C_];
}

__device__ __forceinline__ void k2b_step(const float* buf, float bias,
                                         float& m, float& sub, unsigned& word)
{
    word = 0u;
    #pragma unroll
    for (int k = 0; k < 32; ++k) {
        m = BETA * m + (buf[k] + bias) - sub;
        const unsigned neg = (unsigned)(__float_as_int(THR - m) >> 31);  // all-ones iff m > THR
        sub = __uint_as_float(neg & 0x3F400000u);                        // 0.75f or 0.0f (exact)
        word |= (neg & 1u) << k;
    }
}

__global__ void __launch_bounds__(256) k2b_scan(const float* __restrict__ b_tx,
                                                const float* __restrict__ b_rx)
{
    const int s = blockIdx.x, c = threadIdx.x;
    const bool is_rx = (s >= S_RX0);
    const float bias = is_rx ? b_rx[c] : b_tx[c];
    const float* ap = g_acc + (size_t)s * T_ * C_ + c;
    const unsigned tb = is_rx ? ((unsigned)(s - S_RX0) * C_ + c) * 32u : 0u;

    float m = 0.0f, sub = 0.0f;
    int cnt = 0;
    float bufA[32], bufB[32];

    k2b_load(bufA, ap, 0);
    #pragma unroll 1
    for (int i = 0; i < 16; ++i) {
        unsigned w0, w1;
        k2b_load(bufB, ap, 2 * i + 1);
        k2b_step(bufA, bias, m, sub, w0);
        if (is_rx) g_trace[tb + 2 * i] = w0;
        cnt += __popc(w0);
        if (i < 15) k2b_load(bufA, ap, 2 * i + 2);
        k2b_step(bufB, bias, m, sub, w1);
        if (is_rx) g_trace[tb + 2 * i + 1] = w1;
        cnt += __popc(w1);
    }
    g_spkcnt[s * C_ + c] = cnt;
}

// ============================================================================
// K3: expand rx spike bits -> float32 trace in d_out (coalesced LUT expansion)
// ============================================================================
__global__ void k3_expand(float* __restrict__ out)
{
    __shared__ float4 lut[16];
    if (threadIdx.x < 16)
        lut[threadIdx.x] = make_float4((float)(threadIdx.x & 1), (float)((threadIdx.x >> 1) & 1),
                                       (float)((threadIdx.x >> 2) & 1), (float)((threadIdx.x >> 3) & 1));
    __syncthreads();

    const int row = blockIdx.x * 8 + (threadIdx.x >> 5);   // 0..32767
    const int l   = threadIdx.x & 31;
    const unsigned word = g_trace[(size_t)row * 32 + l];
    float4* dst = (float4*)(out + OUT_RX + (size_t)row * T_);
    #pragma unroll
    for (int k = 0; k < 8; k++) {
        const int t4   = k * 32 + l;
        const unsigned wsrc = __shfl_sync(0xffffffffu, word, t4 >> 3);
        const unsigned nib  = (wsrc >> ((t4 & 7) * 4)) & 0xFu;
        dst[t4] = lut[nib];
    }
}

// ============================================================================
// K4a: features + layernorm + spike_proxy
// ============================================================================
__device__ __forceinline__ float blk_sum(float v, float* red, int c)
{
    red[c] = v; __syncthreads();
    #pragma unroll
    for (int off = 128; off > 0; off >>= 1) {
        if (c < off) red[c] += red[c + off];
        __syncthreads();
    }
    float s = red[0]; __syncthreads();
    return s;
}

__global__ void k4a_feat(float* __restrict__ out)
{
    __shared__ float red[256];
    const int b = blockIdx.x, c = threadIdx.x;
    const int cd = g_spkcnt[b * C_ + c];
    const int cl = g_spkcnt[(S_RX0 + b * 2 + 0) * C_ + c];
    const int cr = g_spkcnt[(S_RX0 + b * 2 + 1) * C_ + c];

    out[OUT_PX + (size_t)(b * 2 + 0) * C_ + c] = (float)cl;
    out[OUT_PX + (size_t)(b * 2 + 1) * C_ + c] = (float)cr;

    float f[3];
    f[0] = (float)cd        * (1.0f / 1024.0f);
    f[1] = (float)(cl - cr) * (1.0f / 1024.0f);
    f[2] = (float)(cl + cr) * (1.0f / 1024.0f);

    #pragma unroll
    for (int typ = 0; typ < 3; typ++) {
        const float mu = blk_sum(f[typ], red, c) * (1.0f / 256.0f);
        const float xc = f[typ] - mu;
        const float var = blk_sum(xc * xc, red, c) * (1.0f / 256.0f);
        g_feat[(typ * B_ + b) * C_ + c] = xc / sqrtf(var + 1e-5f);
    }
}

// ============================================================================
// K4b: heads — [64x256]@[256x512]^T + bias, gain, residual, relu.
// ============================================================================
__global__ void k4b_head(const float* __restrict__ Wd, const float* __restrict__ bd,
                         const float* __restrict__ Wa, const float* __restrict__ ba,
                         const float* __restrict__ We, const float* __restrict__ be,
                         const float* __restrict__ base_d, const float* __restrict__ base_a,
                         const float* __restrict__ base_e,
                         const float* __restrict__ gd, const float* __restrict__ ga,
                         const float* __restrict__ ge,
                         float* __restrict__ out)
{
    extern __shared__ float x_sh[];   // 64*256 floats
    const int typ = blockIdx.x >> 6;
    const int h0  = (blockIdx.x & 63) * 8;

    const float* feat = g_feat + (size_t)typ * B_ * C_;
    for (int i = threadIdx.x; i < B_ * C_; i += 256) x_sh[i] = feat[i];
    __syncthreads();

    const float* Wm   = (typ == 0) ? Wd : (typ == 1) ? Wa : We;
    const float* bm   = (typ == 0) ? bd : (typ == 1) ? ba : be;
    const float* bsp  = (typ == 0) ? base_d : (typ == 1) ? base_a : base_e;
    const float  g    = (typ == 0) ? *gd : (typ == 1) ? *ga : *ge;
    const float  sg   = 0.3f / (1.0f + expf(-g));
    const size_t ooff = (typ == 0) ? OUT_D : (typ == 1) ? OUT_A : OUT_E;

    const int lane = threadIdx.x & 31;
    const int h    = h0 + (threadIdx.x >> 5);

    const float4* wrow = (const float4*)(Wm + (size_t)h * C_);
    const float4 w0 = wrow[lane * 2];
    const float4 w1 = wrow[lane * 2 + 1];
    const float  bh = bm[h];

    for (int b = 0; b < B_; b++) {
        const float4* xb = (const float4*)(x_sh + b * C_ + lane * 8);
        const float4 x0 = xb[0], x1 = xb[1];
        float p = w0.x * x0.x + w0.y * x0.y + w0.z * x0.z + w0.w * x0.w
                + w1.x * x1.x + w1.y * x1.y + w1.z * x1.z + w1.w * x1.w;
        #pragma unroll
        for (int off = 16; off > 0; off >>= 1)
            p += __shfl_xor_sync(0xffffffffu, p, off);
        if (lane == 0) {
            const float r = p + bh;
            const float v = bsp[(size_t)b * H_ + h] + sg * r;
            out[ooff + (size_t)b * H_ + h] = v > 0.0f ? v : 0.0f;
        }
    }
}

// ============================================================================
extern "C" void kernel_launch(void* const* d_in, const int* in_sizes, int n_in,
                              void* d_out, int out_size)
{
    const float* tx    = (const float*)d_in[0];
    const float* rxsp  = (const float*)d_in[1];
    const float* bsd   = (const float*)d_in[2];
    const float* bsa   = (const float*)d_in[3];
    const float* bse   = (const float*)d_in[4];
    const float* W_tx  = (const float*)d_in[5];
    const float* b_tx  = (const float*)d_in[6];
    const float* W_rx  = (const float*)d_in[7];
    const float* b_rx  = (const float*)d_in[8];
    const float* Wd    = (const float*)d_in[9];
    const float* bd    = (const float*)d_in[10];
    const float* Wa    = (const float*)d_in[11];
    const float* ba    = (const float*)d_in[12];
    const float* We    = (const float*)d_in[13];
    const float* be    = (const float*)d_in[14];
    const float* gd    = (const float*)d_in[15];
    const float* ga    = (const float*)d_in[16];
    const float* ge    = (const float*)d_in[17];
    float* out = (float*)d_out;

    static bool attr_set = false;
    if (!attr_set) {
        cudaFuncSetAttribute(k2a_mix, cudaFuncAttributeMaxDynamicSharedMemorySize, 98832);
        cudaFuncSetAttribute(k4b_head, cudaFuncAttributeMaxDynamicSharedMemorySize, 65536);
        attr_set = true;
    }

    k0q<<<dim3(2, 4), 256>>>(W_tx, W_rx);
    k1_pack<<<S_TOT * 32, 256>>>(tx, rxsp);
    k2a_mix<<<dim3(T_ / TT, C_ / OB, S_TOT), 256, 98832>>>();
    k2b_scan<<<192, 256>>>(b_tx, b_rx);
    k3_expand<<<4096, 256>>>(out);
    k4a_feat<<<B_, 256>>>(out);
    k4b_head<<<3 * 64, 256, 65536>>>(Wd, bd, Wa, ba, We, be, bsd, bsa, bse, gd, ga, ge, out);
}

// round 16
// speedup vs baseline: 1.1167x; 1.0428x over previous
#include <cuda_runtime.h>
#include <cstdint>
#include <math.h>

#define B_    64
#define C_    256
#define T_    1024
#define H_    512
#define S_TOT 192
#define S_RX0 64
#define BETA  0.9f
#define THR   0.75f
#define LCAP  120      // per-timestep active-index list capacity (u16, padded to mult of 4)
#define TT    128      // timesteps per k2a CTA tile
#define OB    64       // output channels per k2a CTA
#define WQN   16964    // ints per W image block (257*66 = 16962, +2 pad -> 4241 uint4)

// ---- output layout (flattened tuple, float32) ----
#define OUT_D  0
#define OUT_A  (B_*H_)
#define OUT_E  (2*B_*H_)
#define OUT_RX (3*B_*H_)
#define OUT_PX (3*B_*H_ + B_*2*C_*T_)

// ---- static device scratch ----
__device__ float          g_acc   [(size_t)S_TOT * T_ * C_];  // mixed (pre-bias) [s][t][c]
__device__ unsigned int   g_trace [128 * C_ * 32];            // rx spike bits [rb][c][t/32]
__device__ int            g_spkcnt[S_TOT * C_];
__device__ float          g_feat  [3 * B_ * C_];
__device__ uint4          g_idx_w [S_TOT * T_ * (LCAP/8)];    // u16 index lists (premul x33)
__device__ unsigned short g_cnt   [S_TOT * T_];
__device__ __align__(16) int g_Wq [8 * WQN];                  // quantized W images [img2][oblk4]

// ============================================================================
// K0q: pre-quantize W_tx / W_rx into smem-image layout: per (img, o-block),
// W_q[c*66 + r] = rint(W[(o0+r)*256 + c] * 2^30), plus zero row + pad.
// grid dim3(2,4) x 256 threads.
// ============================================================================
__global__ void k0q(const float* __restrict__ W_tx, const float* __restrict__ W_rx)
{
    const int img = blockIdx.x, ob = blockIdx.y;
    const float* W = img ? W_rx : W_tx;
    int* dst = g_Wq + (img * 4 + ob) * WQN;
    const int o0 = ob * OB;

    #pragma unroll 4
    for (int idx = threadIdx.x; idx < OB * C_; idx += 256) {
        const int r = idx >> 8, c = idx & 255;
        dst[c * 66 + r] = __float2int_rn(W[(size_t)(o0 + r) * C_ + c] * 1073741824.0f);
    }
    if (threadIdx.x < 68) dst[256 * 66 + threadIdx.x] = 0;   // zero row + pad
}

// ============================================================================
// K1 v2: active-channel index lists; float4 gmem loads (8/thread).
// Indices PRE-MULTIPLIED by 33. Pad to mult of 4.
// grid: 192*32 CTAs, 256 threads. CTA = (s, 32-timestep tile)
// ============================================================================
__global__ void k1_pack(const float* __restrict__ tx, const float* __restrict__ rxsp)
{
    __shared__ float tile[256 * 33];
    __shared__ __align__(16) unsigned short lists[32 * LCAP];
    __shared__ int cnts[32];

    const int s  = blockIdx.x >> 5;
    const int t0 = (blockIdx.x & 31) * 32;
    const float* base = (s < S_RX0) ? (tx + (size_t)s * C_ * T_)
                                    : (rxsp + (size_t)(s - S_RX0) * C_ * T_);
    const int w = threadIdx.x >> 5, l = threadIdx.x & 31;

    // float4 loads: thread -> (c = tid>>3 + i*32, tq = tid&7); 128B-coalesced.
    {
        const int cl = threadIdx.x >> 3, tq = threadIdx.x & 7;
        #pragma unroll
        for (int i = 0; i < 8; i++) {
            const int c = cl + i * 32;
            const float4 f = *(const float4*)(base + (size_t)c * T_ + t0 + tq * 4);
            float* dstp = tile + c * 33 + tq * 4;
            dstp[0] = f.x; dstp[1] = f.y; dstp[2] = f.z; dstp[3] = f.w;
        }
    }
    __syncthreads();

    for (int tt = w * 4; tt < w * 4 + 4; tt++) {
        int cnt = 0;
        #pragma unroll
        for (int g = 0; g < 8; g++) {
            float v = tile[(g * 32 + l) * 33 + tt];
            unsigned m = __ballot_sync(0xffffffffu, v > 0.5f);
            if (v > 0.5f) {
                int pos = cnt + __popc(m & ((1u << l) - 1u));
                if (pos < LCAP) lists[tt * LCAP + pos] = (unsigned short)((g * 32 + l) * 33);
            }
            cnt += __popc(m);
        }
        if (cnt > 116) cnt = 116;               // astronomically unlikely
        int padded = (cnt + 3) & ~3;
        if (l < padded - cnt) lists[tt * LCAP + cnt + l] = (unsigned short)(256 * 33); // zero row
        if (l == 0) cnts[tt] = padded;
    }
    __syncthreads();

    uint4* dst = g_idx_w + (size_t)(s * T_ + t0) * (LCAP/8);
    const uint4* srcw = (const uint4*)lists;
    for (int i = threadIdx.x; i < 32 * (LCAP/8); i += 256) dst[i] = srcw[i];
    if (threadIdx.x < 32)
        g_cnt[s * T_ + t0 + threadIdx.x] = (unsigned short)cnts[threadIdx.x];
}

// ============================================================================
// K2a v7: sparse mix, EXACT uint32 accumulation of pre-quantized W.
// CTA = (s, o-block, 128-t tile), full grid (8 x 4 x 192), sequential launch.
// 256 threads, warp = 16 t's, lane = 2 outputs via LDS.64. 2 CTAs/SM.
// Inner loop: 8-active groups (unroll 2) + optional 4-active epilogue.
// smem: W image 67856B @0; lists 30720B @67856; cnt 128*u16 @98576. = 98832.
// ============================================================================
__global__ void __launch_bounds__(256) k2a_mix()
{
    extern __shared__ unsigned char smem_raw[];
    int*            W_shi  = (int*)smem_raw;
    unsigned short* lists  = (unsigned short*)(smem_raw + 67856);
    unsigned short* cnt_sh = (unsigned short*)(smem_raw + 98576);

    const int tid = threadIdx.x;
    const int s   = blockIdx.z;
    const int ob  = blockIdx.y;
    const int t0  = blockIdx.x * TT;
    const int o0  = ob * OB;
    const int img = (s < S_RX0) ? 0 : 1;

    // ---- prologue: copy pre-quantized W image (4241 uint4, L2-resident)
    {
        const uint4* wsrc = (const uint4*)(g_Wq + (img * 4 + ob) * WQN);
        uint4* wdst = (uint4*)W_shi;
        #pragma unroll 4
        for (int i = tid; i < 4241; i += 256) wdst[i] = wsrc[i];
    }
    // ---- stage lists + counts for this 128-t tile
    {
        const uint4* src = g_idx_w + (size_t)(s * T_ + t0) * (LCAP/8);
        uint4* dstl = (uint4*)lists;
        #pragma unroll 2
        for (int i = tid; i < TT * (LCAP/8); i += 256) dstl[i] = src[i];
        if (tid < TT) cnt_sh[tid] = g_cnt[s * T_ + t0 + tid];
    }
    __syncthreads();

    const int w = tid >> 5, lane = tid & 31;
    const uint2* Wt2 = (const uint2*)W_shi + lane;   // lane's int2 column

    #pragma unroll 1
    for (int tslot = 0; tslot < TT / 8; ++tslot) {
        const int tt = w * (TT / 8) + tslot;
        const int cnt = cnt_sh[tt];
        const int n8 = cnt >> 3;
        const unsigned short* lw16 = lists + tt * LCAP;
        const uint4* lw = (const uint4*)lw16;
        unsigned a0x = 0u, a0y = 0u, a1x = 0u, a1y = 0u;
        unsigned a2x = 0u, a2y = 0u, a3x = 0u, a3y = 0u;
        #pragma unroll 2
        for (int j = 0; j < n8; ++j) {
            uint4 v = lw[j];
            uint2 w0 = Wt2[v.x & 0xffffu];  a0x += w0.x; a0y += w0.y;
            uint2 w1 = Wt2[v.x >> 16];      a1x += w1.x; a1y += w1.y;
            uint2 w2 = Wt2[v.y & 0xffffu];  a2x += w2.x; a2y += w2.y;
            uint2 w3 = Wt2[v.y >> 16];      a3x += w3.x; a3y += w3.y;
            uint2 w4 = Wt2[v.z & 0xffffu];  a0x += w4.x; a0y += w4.y;
            uint2 w5 = Wt2[v.z >> 16];      a1x += w5.x; a1y += w5.y;
            uint2 w6 = Wt2[v.w & 0xffffu];  a2x += w6.x; a2y += w6.y;
            uint2 w7 = Wt2[v.w >> 16];      a3x += w7.x; a3y += w7.y;
        }
        if (cnt & 4) {   // 4-active epilogue group (pad-4 lists)
            const uint2 v = *(const uint2*)(lw16 + (n8 << 3));
            uint2 w0 = Wt2[v.x & 0xffffu];  a0x += w0.x; a0y += w0.y;
            uint2 w1 = Wt2[v.x >> 16];      a1x += w1.x; a1y += w1.y;
            uint2 w2 = Wt2[v.y & 0xffffu];  a2x += w2.x; a2y += w2.y;
            uint2 w3 = Wt2[v.y >> 16];      a3x += w3.x; a3y += w3.y;
        }
        const int sx = (int)((a0x + a1x) + (a2x + a3x));
        const int sy = (int)((a0y + a1y) + (a2y + a3y));
        float2 r;
        r.x = (float)sx * 0x1p-30f;
        r.y = (float)sy * 0x1p-30f;
        *(float2*)(g_acc + (size_t)(s * T_ + t0 + tt) * C_ + o0 + 2 * lane) = r;
    }
}

// ============================================================================
// K2b v3: LIF recurrence; bias folded into load phase, FSET-based spike
// (sub ready at m+8 instead of m+12 — values bit-identical).
// grid 192 x 256; CTA per sequence, thread per channel.
// ============================================================================
__device__ __forceinline__ void k2b_load(float* buf, const float* ap, int t32, float bias)
{
    #pragma unroll
    for (int k = 0; k < 32; ++k)
        buf[k] = ap[(size_t)(t32 * 32 + k) * C_] + bias;
}

__device__ __forceinline__ void k2b_step(const float* buf,
                                         float& m, float& sub, unsigned& word)
{
    word = 0u;
    #pragma unroll
    for (int k = 0; k < 32; ++k) {
        m = BETA * m + buf[k] - sub;
        unsigned d;
        asm("set.u32.f32.gt %0, %1, %2;" : "=r"(d) : "f"(m), "f"(THR));  // 0xFFFFFFFF iff m > THR
        sub = __uint_as_float(d & 0x3F400000u);                           // 0.75f or 0.0f (exact)
        word |= (d & 1u) << k;
    }
}

__global__ void __launch_bounds__(256) k2b_scan(const float* __restrict__ b_tx,
                                                const float* __restrict__ b_rx)
{
    const int s = blockIdx.x, c = threadIdx.x;
    const bool is_rx = (s >= S_RX0);
    const float bias = is_rx ? b_rx[c] : b_tx[c];
    const float* ap = g_acc + (size_t)s * T_ * C_ + c;
    const unsigned tb = is_rx ? ((unsigned)(s - S_RX0) * C_ + c) * 32u : 0u;

    float m = 0.0f, sub = 0.0f;
    int cnt = 0;
    float bufA[32], bufB[32];

    k2b_load(bufA, ap, 0, bias);
    #pragma unroll 1
    for (int i = 0; i < 16; ++i) {
        unsigned w0, w1;
        k2b_load(bufB, ap, 2 * i + 1, bias);
        k2b_step(bufA, m, sub, w0);
        if (is_rx) g_trace[tb + 2 * i] = w0;
        cnt += __popc(w0);
        if (i < 15) k2b_load(bufA, ap, 2 * i + 2, bias);
        k2b_step(bufB, m, sub, w1);
        if (is_rx) g_trace[tb + 2 * i + 1] = w1;
        cnt += __popc(w1);
    }
    g_spkcnt[s * C_ + c] = cnt;
}

// ============================================================================
// K3: expand rx spike bits -> float32 trace in d_out (coalesced LUT expansion)
// ============================================================================
__global__ void k3_expand(float* __restrict__ out)
{
    __shared__ float4 lut[16];
    if (threadIdx.x < 16)
        lut[threadIdx.x] = make_float4((float)(threadIdx.x & 1), (float)((threadIdx.x >> 1) & 1),
                                       (float)((threadIdx.x >> 2) & 1), (float)((threadIdx.x >> 3) & 1));
    __syncthreads();

    const int row = blockIdx.x * 8 + (threadIdx.x >> 5);   // 0..32767
    const int l   = threadIdx.x & 31;
    const unsigned word = g_trace[(size_t)row * 32 + l];
    float4* dst = (float4*)(out + OUT_RX + (size_t)row * T_);
    #pragma unroll
    for (int k = 0; k < 8; k++) {
        const int t4   = k * 32 + l;
        const unsigned wsrc = __shfl_sync(0xffffffffu, word, t4 >> 3);
        const unsigned nib  = (wsrc >> ((t4 & 7) * 4)) & 0xFu;
        dst[t4] = lut[nib];
    }
}

// ============================================================================
// K4a: features + layernorm + spike_proxy
// ============================================================================
__device__ __forceinline__ float blk_sum(float v, float* red, int c)
{
    red[c] = v; __syncthreads();
    #pragma unroll
    for (int off = 128; off > 0; off >>= 1) {
        if (c < off) red[c] += red[c + off];
        __syncthreads();
    }
    float s = red[0]; __syncthreads();
    return s;
}

__global__ void k4a_feat(float* __restrict__ out)
{
    __shared__ float red[256];
    const int b = blockIdx.x, c = threadIdx.x;
    const int cd = g_spkcnt[b * C_ + c];
    const int cl = g_spkcnt[(S_RX0 + b * 2 + 0) * C_ + c];
    const int cr = g_spkcnt[(S_RX0 + b * 2 + 1) * C_ + c];

    out[OUT_PX + (size_t)(b * 2 + 0) * C_ + c] = (float)cl;
    out[OUT_PX + (size_t)(b * 2 + 1) * C_ + c] = (float)cr;

    float f[3];
    f[0] = (float)cd        * (1.0f / 1024.0f);
    f[1] = (float)(cl - cr) * (1.0f / 1024.0f);
    f[2] = (float)(cl + cr) * (1.0f / 1024.0f);

    #pragma unroll
    for (int typ = 0; typ < 3; typ++) {
        const float mu = blk_sum(f[typ], red, c) * (1.0f / 256.0f);
        const float xc = f[typ] - mu;
        const float var = blk_sum(xc * xc, red, c) * (1.0f / 256.0f);
        g_feat[(typ * B_ + b) * C_ + c] = xc / sqrtf(var + 1e-5f);
    }
}

// ============================================================================
// K4b: heads — [64x256]@[256x512]^T + bias, gain, residual, relu.
// ============================================================================
__global__ void k4b_head(const float* __restrict__ Wd, const float* __restrict__ bd,
                         const float* __restrict__ Wa, const float* __restrict__ ba,
                         const float* __restrict__ We, const float* __restrict__ be,
                         const float* __restrict__ base_d, const float* __restrict__ base_a,
                         const float* __restrict__ base_e,
                         const float* __restrict__ gd, const float* __restrict__ ga,
                         const float* __restrict__ ge,
                         float* __restrict__ out)
{
    extern __shared__ float x_sh[];   // 64*256 floats
    const int typ = blockIdx.x >> 6;
    const int h0  = (blockIdx.x & 63) * 8;

    const float* feat = g_feat + (size_t)typ * B_ * C_;
    for (int i = threadIdx.x; i < B_ * C_; i += 256) x_sh[i] = feat[i];
    __syncthreads();

    const float* Wm   = (typ == 0) ? Wd : (typ == 1) ? Wa : We;
    const float* bm   = (typ == 0) ? bd : (typ == 1) ? ba : be;
    const float* bsp  = (typ == 0) ? base_d : (typ == 1) ? base_a : base_e;
    const float  g    = (typ == 0) ? *gd : (typ == 1) ? *ga : *ge;
    const float  sg   = 0.3f / (1.0f + expf(-g));
    const size_t ooff = (typ == 0) ? OUT_D : (typ == 1) ? OUT_A : OUT_E;

    const int lane = threadIdx.x & 31;
    const int h    = h0 + (threadIdx.x >> 5);

    const float4* wrow = (const float4*)(Wm + (size_t)h * C_);
    const float4 w0 = wrow[lane * 2];
    const float4 w1 = wrow[lane * 2 + 1];
    const float  bh = bm[h];

    for (int b = 0; b < B_; b++) {
        const float4* xb = (const float4*)(x_sh + b * C_ + lane * 8);
        const float4 x0 = xb[0], x1 = xb[1];
        float p = w0.x * x0.x + w0.y * x0.y + w0.z * x0.z + w0.w * x0.w
                + w1.x * x1.x + w1.y * x1.y + w1.z * x1.z + w1.w * x1.w;
        #pragma unroll
        for (int off = 16; off > 0; off >>= 1)
            p += __shfl_xor_sync(0xffffffffu, p, off);
        if (lane == 0) {
            const float r = p + bh;
            const float v = bsp[(size_t)b * H_ + h] + sg * r;
            out[ooff + (size_t)b * H_ + h] = v > 0.0f ? v : 0.0f;
        }
    }
}

// ============================================================================
extern "C" void kernel_launch(void* const* d_in, const int* in_sizes, int n_in,
                              void* d_out, int out_size)
{
    const float* tx    = (const float*)d_in[0];
    const float* rxsp  = (const float*)d_in[1];
    const float* bsd   = (const float*)d_in[2];
    const float* bsa   = (const float*)d_in[3];
    const float* bse   = (const float*)d_in[4];
    const float* W_tx  = (const float*)d_in[5];
    const float* b_tx  = (const float*)d_in[6];
    const float* W_rx  = (const float*)d_in[7];
    const float* b_rx  = (const float*)d_in[8];
    const float* Wd    = (const float*)d_in[9];
    const float* bd    = (const float*)d_in[10];
    const float* Wa    = (const float*)d_in[11];
    const float* ba    = (const float*)d_in[12];
    const float* We    = (const float*)d_in[13];
    const float* be    = (const float*)d_in[14];
    const float* gd    = (const float*)d_in[15];
    const float* ga    = (const float*)d_in[16];
    const float* ge    = (const float*)d_in[17];
    float* out = (float*)d_out;

    static bool attr_set = false;
    if (!attr_set) {
        cudaFuncSetAttribute(k2a_mix, cudaFuncAttributeMaxDynamicSharedMemorySize, 98832);
        cudaFuncSetAttribute(k4b_head, cudaFuncAttributeMaxDynamicSharedMemorySize, 65536);
        attr_set = true;
    }

    k0q<<<dim3(2, 4), 256>>>(W_tx, W_rx);
    k1_pack<<<S_TOT * 32, 256>>>(tx, rxsp);
    k2a_mix<<<dim3(T_ / TT, C_ / OB, S_TOT), 256, 98832>>>();
    k2b_scan<<<192, 256>>>(b_tx, b_rx);
    k3_expand<<<4096, 256>>>(out);
    k4a_feat<<<B_, 256>>>(out);
    k4b_head<<<3 * 64, 256, 65536>>>(Wd, bd, Wa, ba, We, be, bsd, bsa, bse, gd, ga, ge, out);
}